// round 13
// baseline (speedup 1.0000x reference)
#include <cuda_runtime.h>
#include <cuda_fp16.h>
#include <cstdint>
#include <cstddef>

#define MTOT 2048
#define NTOT 4096
#define KTOT 4352
#define HDIM 1024
#define XDIM 2304

#define BM 128
#define BN 256
#define BK 128                                  // halves per K-tile
#define ROWB 272                                // 256B data + 16B pad
#define A_BYTES (BM * ROWB)                     // 34816
#define B_BYTES (BN * ROWB)                     // 69632
#define STAGE_BYTES (A_BYTES + B_BYTES)         // 104448
#define BIAS_BYTE_OFF (2 * STAGE_BYTES)         // 208896
#define SMEM_BYTES (BIAS_BYTE_OFF + 1024)       // 209920
#define KTILES (KTOT / BK)                      // 34

__device__ __half g_Z[(size_t)MTOT * KTOT];

__device__ __forceinline__ void cp16(void* sdst, const void* gsrc) {
    uint32_t s = (uint32_t)__cvta_generic_to_shared(sdst);
    asm volatile("cp.async.cg.shared.global [%0], [%1], 16;" :: "r"(s), "l"(gsrc));
}

__device__ __forceinline__ void ldsm4(uint32_t addr, uint32_t* r) {
    asm volatile("ldmatrix.sync.aligned.m8n8.x4.shared.b16 {%0,%1,%2,%3}, [%4];"
                 : "=r"(r[0]), "=r"(r[1]), "=r"(r[2]), "=r"(r[3]) : "r"(addr));
}

__device__ __forceinline__ uint2 pack8(float4 f0, float4 f1) {
    __half2 h0 = __floats2half2_rn(f0.x, f0.y);
    __half2 h1 = __floats2half2_rn(f0.z, f0.w);
    __half2 h2 = __floats2half2_rn(f1.x, f1.y);
    __half2 h3 = __floats2half2_rn(f1.z, f1.w);
    uint2 u;
    u.x = (*reinterpret_cast<uint32_t*>(&h0)) ;
    u.y = (*reinterpret_cast<uint32_t*>(&h1)) ;
    uint2 v;
    v.x = (*reinterpret_cast<uint32_t*>(&h2));
    v.y = (*reinterpret_cast<uint32_t*>(&h3));
    // return two uint2s via one uint4 path below instead
    (void)v;
    return u;
}

__device__ __forceinline__ float sigm(float v) { return 1.0f / (1.0f + __expf(-v)); }

// ---------------- Z-only convert kernel (grid-stride) ----------------
#define C4_PER_ROW (KTOT / 4)                   // 1088
#define CONVZ_TOTAL (MTOT * C4_PER_ROW)

__global__ __launch_bounds__(256) void conv_z(
    const float* __restrict__ x, const float* __restrict__ pt, const float* __restrict__ pl)
{
    for (int idx = blockIdx.x * blockDim.x + threadIdx.x; idx < CONVZ_TOTAL;
         idx += gridDim.x * blockDim.x) {
        int y = idx / C4_PER_ROW;
        int c4 = idx - y * C4_PER_ROW;
        int col = c4 * 4;

        const float* src;
        int cc;
        if (col < XDIM)             { src = x  + (size_t)y * XDIM; cc = col; }
        else if (col < XDIM + HDIM) { src = pt + (size_t)y * HDIM; cc = col - XDIM; }
        else                        { src = pl + (size_t)y * HDIM; cc = col - XDIM - HDIM; }

        float4 v = *reinterpret_cast<const float4*>(src + cc);
        __half2 h0 = __floats2half2_rn(v.x, v.y);
        __half2 h1 = __floats2half2_rn(v.z, v.w);
        uint2 u;
        u.x = *reinterpret_cast<uint32_t*>(&h0);
        u.y = *reinterpret_cast<uint32_t*>(&h1);
        *reinterpret_cast<uint2*>(g_Z + (size_t)y * KTOT + col) = u;
    }
}

// ---------------- fp16 GEMM + fused LSTM, in-loader W conversion ----------------
__global__ __launch_bounds__(256, 1) void gemm_lstm(
    const float* __restrict__ old_state,
    const float* __restrict__ Wi, const float* __restrict__ Wf,
    const float* __restrict__ Wo, const float* __restrict__ Ws,
    const float* __restrict__ bi, const float* __restrict__ bf,
    const float* __restrict__ bo, const float* __restrict__ bs,
    float* __restrict__ out)
{
    extern __shared__ __align__(16) char smem[];
    const uint32_t smem_u = (uint32_t)__cvta_generic_to_shared(smem);

    const int tid  = threadIdx.x;
    const int lane = tid & 31;
    const int warp = tid >> 5;
    const int wm   = (warp & 1) * 64;
    const int wn   = (warp >> 1) * 64;
    const int m0   = blockIdx.y * BM;
    const int n_tile = blockIdx.x;
    const int h0   = n_tile * 64;

    const __half* gA = g_Z + (size_t)m0 * KTOT;

    float* bias_sm = reinterpret_cast<float*>(smem + BIAS_BYTE_OFF);   // [64][4]
    {
        int hl = tid >> 2, gate = tid & 3;
        const float* b = (gate == 0) ? bi : (gate == 1) ? bf : (gate == 2) ? bo : bs;
        bias_sm[tid] = b[h0 + hl];
    }

    // loader: rows of 256B = 16 chunks; 256 threads = 16 rows/iter
    const int lr = tid >> 4;                 // 0..15
    const int lcb = (tid & 15) << 4;         // byte chunk 0..240 (fp16 row)

    // per-thread W source: gate fixed (= lr&3), rows advance by 4 in h per i
    const int my_gate = lr & 3;
    const float* Wg = (my_gate == 0) ? Wi : (my_gate == 1) ? Wf : (my_gate == 2) ? Wo : Ws;
    // base row h for i=0, plus float-col offset lcb/2
    const float* wsrc0 = Wg + (size_t)(h0 + (lr >> 2)) * KTOT + (lcb >> 1);

    const uint32_t aOff = (uint32_t)((wm + (lane & 7) + ((lane >> 3) & 1) * 8) * ROWB
                                     + (lane >> 4) * 16);
    const uint32_t bOff = (uint32_t)(A_BYTES
                                     + (wn + (lane & 7) + ((lane >> 4) & 1) * 8) * ROWB
                                     + ((lane >> 3) & 1) * 16);

    float acc[4][8][4];
#pragma unroll
    for (int t = 0; t < 4; t++)
#pragma unroll
        for (int u = 0; u < 8; u++)
#pragma unroll
            for (int v = 0; v < 4; v++) acc[t][u][v] = 0.f;

    auto load_A = [&](int kt) {
        char* As = smem + (kt & 1) * STAGE_BYTES;
        const int k0 = kt * BK;
#pragma unroll
        for (int i = 0; i < 8; i++) {
            int r = lr + i * 16;
            cp16(As + r * ROWB + lcb, (const char*)(gA + (size_t)r * KTOT + k0) + lcb);
        }
    };

    // B staging (4 chunks per group, 4 groups per stage)
    float4 stg[8];
    auto ldg_B = [&](int kt, int g) {
        const float* p = wsrc0 + (size_t)kt * BK + (size_t)(g * 4) * 4 * KTOT;
#pragma unroll
        for (int c = 0; c < 4; c++) {
            stg[2 * c]     = __ldg(reinterpret_cast<const float4*>(p));
            stg[2 * c + 1] = __ldg(reinterpret_cast<const float4*>(p + 4));
            p += (size_t)4 * KTOT;
        }
    };
    auto sts_B = [&](int kt, int g) {
        char* Bs = smem + (kt & 1) * STAGE_BYTES + A_BYTES;
#pragma unroll
        for (int c = 0; c < 4; c++) {
            int i = g * 4 + c;
            int r = lr + i * 16;
            float4 f0 = stg[2 * c], f1 = stg[2 * c + 1];
            __half2 h0 = __floats2half2_rn(f0.x, f0.y);
            __half2 h1 = __floats2half2_rn(f0.z, f0.w);
            __half2 h2 = __floats2half2_rn(f1.x, f1.y);
            __half2 h3 = __floats2half2_rn(f1.z, f1.w);
            uint4 u;
            u.x = *reinterpret_cast<uint32_t*>(&h0);
            u.y = *reinterpret_cast<uint32_t*>(&h1);
            u.z = *reinterpret_cast<uint32_t*>(&h2);
            u.w = *reinterpret_cast<uint32_t*>(&h3);
            *reinterpret_cast<uint4*>(Bs + r * ROWB + lcb) = u;
        }
    };

    // prologue: stage 0
    load_A(0);
    asm volatile("cp.async.commit_group;");
#pragma unroll
    for (int g = 0; g < 4; g++) { ldg_B(0, g); sts_B(0, g); }

    uint32_t afr[2][4][4], bfr[2][4][4];

    for (int kt = 0; kt < KTILES; kt++) {
        asm volatile("cp.async.wait_group 0;");
        __syncthreads();

        const bool haveNext = (kt + 1 < KTILES);
        if (haveNext) {
            load_A(kt + 1);
            asm volatile("cp.async.commit_group;");
            ldg_B(kt + 1, 0);                    // group 0 LDGs in flight
        }

        const uint32_t stage = smem_u + (uint32_t)((kt & 1) * STAGE_BYTES);
        const uint32_t aBase = stage + aOff;
        const uint32_t bBase = stage + bOff;

        // prefetch ks=0 fragments
#pragma unroll
        for (int t = 0; t < 4; t++) ldsm4(aBase + t * (16 * ROWB), afr[0][t]);
#pragma unroll
        for (int j = 0; j < 4; j++) ldsm4(bBase + j * (16 * ROWB), bfr[0][j]);

#pragma unroll
        for (int ks = 0; ks < 8; ks++) {     // each ks = k16 (32B)
            const int cur = ks & 1, nxt = cur ^ 1;
            if (ks < 7) {
#pragma unroll
                for (int t = 0; t < 4; t++)
                    ldsm4(aBase + (ks + 1) * 32 + t * (16 * ROWB), afr[nxt][t]);
#pragma unroll
                for (int j = 0; j < 4; j++)
                    ldsm4(bBase + (ks + 1) * 32 + j * (16 * ROWB), bfr[nxt][j]);
            }
            if (haveNext && (ks & 1)) {          // ks = 1,3,5,7 -> groups 0..3
                const int g = ks >> 1;
                sts_B(kt + 1, g);
                if (g < 3) ldg_B(kt + 1, g + 1);
            }
#pragma unroll
            for (int t = 0; t < 4; t++)
#pragma unroll
                for (int u = 0; u < 8; u++) {
                    const int j = u >> 1;
                    const uint32_t b0 = (u & 1) ? bfr[cur][j][2] : bfr[cur][j][0];
                    const uint32_t b1 = (u & 1) ? bfr[cur][j][3] : bfr[cur][j][1];
                    asm volatile(
                        "mma.sync.aligned.m16n8k16.row.col.f32.f16.f16.f32 "
                        "{%0,%1,%2,%3},{%4,%5,%6,%7},{%8,%9},{%0,%1,%2,%3};"
                        : "+f"(acc[t][u][0]), "+f"(acc[t][u][1]),
                          "+f"(acc[t][u][2]), "+f"(acc[t][u][3])
                        : "r"(afr[cur][t][0]), "r"(afr[cur][t][1]),
                          "r"(afr[cur][t][2]), "r"(afr[cur][t][3]),
                          "r"(b0), "r"(b1));
                }
        }
    }

    // ---- fused LSTM gate epilogue ----
    const int hadj = (lane & 3) >> 1;
    const int row_sel = (lane & 1) << 3;
#pragma unroll
    for (int t = 0; t < 4; t++) {
        int r_out = m0 + wm + t * 16 + (lane >> 2) + row_sel;
        const float* oldr = old_state + (size_t)r_out * HDIM + h0;
        float*       outr = out       + (size_t)r_out * HDIM + h0;
#pragma unroll
        for (int u = 0; u < 8; u++) {
            float v0 = acc[t][u][0], v1 = acc[t][u][1];
            float v2 = acc[t][u][2], v3 = acc[t][u][3];
            float t0 = (lane & 1) ? v0 : v2;
            float t1 = (lane & 1) ? v1 : v3;
            float e0 = __shfl_xor_sync(0xffffffffu, t0, 1);
            float e1 = __shfl_xor_sync(0xffffffffu, t1, 1);
            float gi, gf, go, gs;
            if (lane & 1) { gi = e0; gf = e1; go = v2; gs = v3; }
            else          { gi = v0; gf = v1; go = e0; gs = e1; }
            int hl = ((wn + u * 8) >> 2) + hadj;
            gi += bias_sm[hl * 4 + 0];
            gf += bias_sm[hl * 4 + 1];
            go += bias_sm[hl * 4 + 2];
            gs += bias_sm[hl * 4 + 3];
            float c  = __ldg(oldr + hl);
            float ns = sigm(gf) * c + sigm(gi) * tanhf(gs);
            outr[hl] = sigm(go) * tanhf(ns);
        }
    }
}

extern "C" void kernel_launch(void* const* d_in, const int* in_sizes, int n_in,
                              void* d_out, int out_size)
{
    const float* x  = (const float*)d_in[0];
    const float* pt = (const float*)d_in[1];
    const float* pl = (const float*)d_in[2];
    const float* os = (const float*)d_in[3];
    const float* Wi = (const float*)d_in[4];
    const float* bi = (const float*)d_in[5];
    const float* Wf = (const float*)d_in[6];
    const float* bf = (const float*)d_in[7];
    const float* Wo = (const float*)d_in[8];
    const float* bo = (const float*)d_in[9];
    const float* Ws = (const float*)d_in[10];
    const float* bs = (const float*)d_in[11];
    float* out = (float*)d_out;

    cudaFuncSetAttribute(gemm_lstm, cudaFuncAttributeMaxDynamicSharedMemorySize, SMEM_BYTES);

    conv_z<<<592, 256>>>(x, pt, pl);
    gemm_lstm<<<dim3(NTOT / BN, MTOT / BM), 256, SMEM_BYTES>>>(
        os, Wi, Wf, Wo, Ws, bi, bf, bo, bs, out);
}

// round 14
// speedup vs baseline: 1.1034x; 1.1034x over previous
#include <cuda_runtime.h>
#include <cuda_fp16.h>
#include <cstdint>
#include <cstddef>

#define MTOT 2048
#define NTOT 4096
#define KTOT 4352
#define HDIM 1024
#define XDIM 2304

#define BM 128
#define BN 256
#define BK 128                                  // halves per K-tile
#define ROWB 272                                // 256B data + 16B pad
#define A_BYTES (BM * ROWB)                     // 34816
#define B_BYTES (BN * ROWB)                     // 69632
#define STAGE_BYTES (A_BYTES + B_BYTES)         // 104448
#define BIAS_BYTE_OFF (2 * STAGE_BYTES)         // 208896
#define SMEM_BYTES (BIAS_BYTE_OFF + 1024)       // 209920
#define KTILES (KTOT / BK)                      // 34

__device__ __half g_Z[(size_t)MTOT * KTOT];
__device__ __half g_WB[(size_t)NTOT * KTOT];

__device__ __forceinline__ void cp16(void* sdst, const void* gsrc) {
    uint32_t s = (uint32_t)__cvta_generic_to_shared(sdst);
    asm volatile("cp.async.cg.shared.global [%0], [%1], 16;" :: "r"(s), "l"(gsrc));
}

__device__ __forceinline__ void ldsm4(uint32_t addr, uint32_t* r) {
    asm volatile("ldmatrix.sync.aligned.m8n8.x4.shared.b16 {%0,%1,%2,%3}, [%4];"
                 : "=r"(r[0]), "=r"(r[1]), "=r"(r[2]), "=r"(r[3]) : "r"(addr));
}

__device__ __forceinline__ float sigm(float v) { return 1.0f / (1.0f + __expf(-v)); }

// ---------------- merged grid-stride convert kernel (32B per iter) ----------------
// dst rows: y<MTOT -> g_Z row y (concat x|pt|pl); else gate-interleaved W row.
#define C8_PER_ROW (KTOT / 8)                   // 544
#define CONV_TOTAL ((MTOT + NTOT) * C8_PER_ROW)

__global__ __launch_bounds__(256) void conv_all(
    const float* __restrict__ x, const float* __restrict__ pt, const float* __restrict__ pl,
    const float* __restrict__ Wi, const float* __restrict__ Wf,
    const float* __restrict__ Wo, const float* __restrict__ Ws)
{
    for (int idx = blockIdx.x * blockDim.x + threadIdx.x; idx < CONV_TOTAL;
         idx += gridDim.x * blockDim.x) {
        int y = idx / C8_PER_ROW;
        int c8 = idx - y * C8_PER_ROW;
        int col = c8 * 8;

        const float* src;
        __half* dst;
        if (y < MTOT) {
            int cc;
            if (col < XDIM)             { src = x  + (size_t)y * XDIM; cc = col; }
            else if (col < XDIM + HDIM) { src = pt + (size_t)y * HDIM; cc = col - XDIM; }
            else                        { src = pl + (size_t)y * HDIM; cc = col - XDIM - HDIM; }
            src += cc - col;
            dst = g_Z + (size_t)y * KTOT;
        } else {
            int g = y - MTOT;
            int n_tile = g >> 8, r = g & 255;
            int h = n_tile * 64 + (r >> 2);
            int gate = r & 3;
            const float* W = (gate == 0) ? Wi : (gate == 1) ? Wf : (gate == 2) ? Wo : Ws;
            src = W + (size_t)h * KTOT;
            dst = g_WB + (size_t)g * KTOT;
        }

        float4 v0 = *reinterpret_cast<const float4*>(src + col);
        float4 v1 = *reinterpret_cast<const float4*>(src + col + 4);
        __half2 h0 = __floats2half2_rn(v0.x, v0.y);
        __half2 h1 = __floats2half2_rn(v0.z, v0.w);
        __half2 h2 = __floats2half2_rn(v1.x, v1.y);
        __half2 h3 = __floats2half2_rn(v1.z, v1.w);
        uint4 u;
        u.x = *reinterpret_cast<uint32_t*>(&h0);
        u.y = *reinterpret_cast<uint32_t*>(&h1);
        u.z = *reinterpret_cast<uint32_t*>(&h2);
        u.w = *reinterpret_cast<uint32_t*>(&h3);
        *reinterpret_cast<uint4*>(dst + col) = u;
    }
}

// ---------------- fp16 GEMM + fused LSTM: 128x256 CTA, 64x64 warp tiles, BK=128 ----------------
__global__ __launch_bounds__(256, 1) void gemm_lstm(
    const float* __restrict__ old_state,
    const float* __restrict__ bi, const float* __restrict__ bf,
    const float* __restrict__ bo, const float* __restrict__ bs,
    float* __restrict__ out)
{
    extern __shared__ __align__(16) char smem[];
    const uint32_t smem_u = (uint32_t)__cvta_generic_to_shared(smem);

    const int tid  = threadIdx.x;
    const int lane = tid & 31;
    const int warp = tid >> 5;
    const int wm   = (warp & 1) * 64;
    const int wn   = (warp >> 1) * 64;
    const int m0   = blockIdx.y * BM;
    const int n_tile = blockIdx.x;
    const int h0   = n_tile * 64;

    const __half* gA = g_Z  + (size_t)m0 * KTOT;
    const __half* gB = g_WB + (size_t)(n_tile * BN) * KTOT;

    float* bias_sm = reinterpret_cast<float*>(smem + BIAS_BYTE_OFF);   // [64][4]
    {
        int hl = tid >> 2, gate = tid & 3;
        const float* b = (gate == 0) ? bi : (gate == 1) ? bf : (gate == 2) ? bo : bs;
        bias_sm[tid] = b[h0 + hl];
    }

    // loader: rows of 256B = 16 chunks; 256 threads = 16 rows/iter
    const int lr = tid >> 4;                 // 0..15
    const int lcb = (tid & 15) << 4;         // 0..240

    const uint32_t aOff = (uint32_t)((wm + (lane & 7) + ((lane >> 3) & 1) * 8) * ROWB
                                     + (lane >> 4) * 16);
    const uint32_t bOff = (uint32_t)(A_BYTES
                                     + (wn + (lane & 7) + ((lane >> 4) & 1) * 8) * ROWB
                                     + ((lane >> 3) & 1) * 16);

    float acc[4][8][4];
#pragma unroll
    for (int t = 0; t < 4; t++)
#pragma unroll
        for (int u = 0; u < 8; u++)
#pragma unroll
            for (int v = 0; v < 4; v++) acc[t][u][v] = 0.f;

    auto load_stage = [&](int kt) {
        char* As = smem + (kt & 1) * STAGE_BYTES;
        char* Bs = As + A_BYTES;
        const int k0 = kt * BK;
#pragma unroll
        for (int i = 0; i < 8; i++) {
            int r = lr + i * 16;
            cp16(As + r * ROWB + lcb, (const char*)(gA + (size_t)r * KTOT + k0) + lcb);
        }
#pragma unroll
        for (int i = 0; i < 16; i++) {
            int r = lr + i * 16;
            cp16(Bs + r * ROWB + lcb, (const char*)(gB + (size_t)r * KTOT + k0) + lcb);
        }
    };

    load_stage(0);
    asm volatile("cp.async.commit_group;");

    uint32_t afr[2][4][4], bfr[2][4][4];

    for (int kt = 0; kt < KTILES; kt++) {
        asm volatile("cp.async.wait_group 0;");
        __syncthreads();

        if (kt + 1 < KTILES) {
            load_stage(kt + 1);
            asm volatile("cp.async.commit_group;");
        }

        const uint32_t stage = smem_u + (uint32_t)((kt & 1) * STAGE_BYTES);
        const uint32_t aBase = stage + aOff;
        const uint32_t bBase = stage + bOff;

        // prefetch ks=0 fragments
#pragma unroll
        for (int t = 0; t < 4; t++) ldsm4(aBase + t * (16 * ROWB), afr[0][t]);
#pragma unroll
        for (int j = 0; j < 4; j++) ldsm4(bBase + j * (16 * ROWB), bfr[0][j]);

#pragma unroll
        for (int ks = 0; ks < 8; ks++) {     // each ks = k16 (32B)
            const int cur = ks & 1, nxt = cur ^ 1;
            if (ks < 7) {
#pragma unroll
                for (int t = 0; t < 4; t++)
                    ldsm4(aBase + (ks + 1) * 32 + t * (16 * ROWB), afr[nxt][t]);
#pragma unroll
                for (int j = 0; j < 4; j++)
                    ldsm4(bBase + (ks + 1) * 32 + j * (16 * ROWB), bfr[nxt][j]);
            }
#pragma unroll
            for (int t = 0; t < 4; t++)
#pragma unroll
                for (int u = 0; u < 8; u++) {
                    const int j = u >> 1;
                    const uint32_t b0 = (u & 1) ? bfr[cur][j][2] : bfr[cur][j][0];
                    const uint32_t b1 = (u & 1) ? bfr[cur][j][3] : bfr[cur][j][1];
                    asm volatile(
                        "mma.sync.aligned.m16n8k16.row.col.f32.f16.f16.f32 "
                        "{%0,%1,%2,%3},{%4,%5,%6,%7},{%8,%9},{%0,%1,%2,%3};"
                        : "+f"(acc[t][u][0]), "+f"(acc[t][u][1]),
                          "+f"(acc[t][u][2]), "+f"(acc[t][u][3])
                        : "r"(afr[cur][t][0]), "r"(afr[cur][t][1]),
                          "r"(afr[cur][t][2]), "r"(afr[cur][t][3]),
                          "r"(b0), "r"(b1));
                }
        }
    }

    // ---- fused LSTM gate epilogue ----
    const int hadj = (lane & 3) >> 1;
    const int row_sel = (lane & 1) << 3;
#pragma unroll
    for (int t = 0; t < 4; t++) {
        int r_out = m0 + wm + t * 16 + (lane >> 2) + row_sel;
        const float* oldr = old_state + (size_t)r_out * HDIM + h0;
        float*       outr = out       + (size_t)r_out * HDIM + h0;
#pragma unroll
        for (int u = 0; u < 8; u++) {
            float v0 = acc[t][u][0], v1 = acc[t][u][1];
            float v2 = acc[t][u][2], v3 = acc[t][u][3];
            float t0 = (lane & 1) ? v0 : v2;
            float t1 = (lane & 1) ? v1 : v3;
            float e0 = __shfl_xor_sync(0xffffffffu, t0, 1);
            float e1 = __shfl_xor_sync(0xffffffffu, t1, 1);
            float gi, gf, go, gs;
            if (lane & 1) { gi = e0; gf = e1; go = v2; gs = v3; }
            else          { gi = v0; gf = v1; go = e0; gs = e1; }
            int hl = ((wn + u * 8) >> 2) + hadj;
            gi += bias_sm[hl * 4 + 0];
            gf += bias_sm[hl * 4 + 1];
            go += bias_sm[hl * 4 + 2];
            gs += bias_sm[hl * 4 + 3];
            float c  = __ldg(oldr + hl);
            float ns = sigm(gf) * c + sigm(gi) * tanhf(gs);
            outr[hl] = sigm(go) * tanhf(ns);
        }
    }
}

extern "C" void kernel_launch(void* const* d_in, const int* in_sizes, int n_in,
                              void* d_out, int out_size)
{
    const float* x  = (const float*)d_in[0];
    const float* pt = (const float*)d_in[1];
    const float* pl = (const float*)d_in[2];
    const float* os = (const float*)d_in[3];
    const float* Wi = (const float*)d_in[4];
    const float* bi = (const float*)d_in[5];
    const float* Wf = (const float*)d_in[6];
    const float* bf = (const float*)d_in[7];
    const float* Wo = (const float*)d_in[8];
    const float* bo = (const float*)d_in[9];
    const float* Ws = (const float*)d_in[10];
    const float* bs = (const float*)d_in[11];
    float* out = (float*)d_out;

    cudaFuncSetAttribute(gemm_lstm, cudaFuncAttributeMaxDynamicSharedMemorySize, SMEM_BYTES);

    conv_all<<<1184, 256>>>(x, pt, pl, Wi, Wf, Wo, Ws);
    gemm_lstm<<<dim3(NTOT / BN, MTOT / BM), 256, SMEM_BYTES>>>(os, bi, bf, bo, bs, out);
}

// round 15
// speedup vs baseline: 1.2260x; 1.1111x over previous
#include <cuda_runtime.h>
#include <cuda_fp16.h>
#include <cstdint>
#include <cstddef>

#define MTOT 2048
#define NTOT 4096
#define KTOT 4352
#define HDIM 1024
#define XDIM 2304
#define KHALF 2176

#define BM 128
#define BN 128
#define BK 64                                   // halves per K-tile
#define ROWB 144                                // 128B data + 16B pad
#define A_BYTES (BM * ROWB)                     // 18432
#define B_BYTES (BN * ROWB)                     // 18432
#define STAGE_BYTES (A_BYTES + B_BYTES)         // 36864
#define SMEM_BYTES (2 * STAGE_BYTES)            // 73728
#define KTILES (KHALF / BK)                     // 34

__device__ __half g_Z[(size_t)MTOT * KTOT];
__device__ __half g_WB[(size_t)NTOT * KTOT];
__device__ float  g_proj[2][(size_t)MTOT * NTOT];   // two split-K partial buffers

__device__ __forceinline__ void cp16(void* sdst, const void* gsrc) {
    uint32_t s = (uint32_t)__cvta_generic_to_shared(sdst);
    asm volatile("cp.async.cg.shared.global [%0], [%1], 16;" :: "r"(s), "l"(gsrc));
}

__device__ __forceinline__ void ldsm4(uint32_t addr, uint32_t* r) {
    asm volatile("ldmatrix.sync.aligned.m8n8.x4.shared.b16 {%0,%1,%2,%3}, [%4];"
                 : "=r"(r[0]), "=r"(r[1]), "=r"(r[2]), "=r"(r[3]) : "r"(addr));
}

__device__ __forceinline__ float sigm(float v) { return 1.0f / (1.0f + __expf(-v)); }

// ---------------- merged grid-stride convert kernel (32B per iter) ----------------
// y<MTOT -> g_Z row (concat x|pt|pl); else g_WB row g = h*4 + gate (global interleave)
#define C8_PER_ROW (KTOT / 8)                   // 544
#define CONV_TOTAL ((MTOT + NTOT) * C8_PER_ROW)

__global__ __launch_bounds__(256) void conv_all(
    const float* __restrict__ x, const float* __restrict__ pt, const float* __restrict__ pl,
    const float* __restrict__ Wi, const float* __restrict__ Wf,
    const float* __restrict__ Wo, const float* __restrict__ Ws)
{
    for (int idx = blockIdx.x * blockDim.x + threadIdx.x; idx < CONV_TOTAL;
         idx += gridDim.x * blockDim.x) {
        int y = idx / C8_PER_ROW;
        int c8 = idx - y * C8_PER_ROW;
        int col = c8 * 8;

        const float* src;
        __half* dst;
        if (y < MTOT) {
            int cc;
            if (col < XDIM)             { src = x  + (size_t)y * XDIM; cc = col; }
            else if (col < XDIM + HDIM) { src = pt + (size_t)y * HDIM; cc = col - XDIM; }
            else                        { src = pl + (size_t)y * HDIM; cc = col - XDIM - HDIM; }
            src += cc - col;
            dst = g_Z + (size_t)y * KTOT;
        } else {
            int g = y - MTOT;
            int h = g >> 2;
            int gate = g & 3;
            const float* W = (gate == 0) ? Wi : (gate == 1) ? Wf : (gate == 2) ? Wo : Ws;
            src = W + (size_t)h * KTOT;
            dst = g_WB + (size_t)g * KTOT;
        }

        float4 v0 = *reinterpret_cast<const float4*>(src + col);
        float4 v1 = *reinterpret_cast<const float4*>(src + col + 4);
        __half2 h0 = __floats2half2_rn(v0.x, v0.y);
        __half2 h1 = __floats2half2_rn(v0.z, v0.w);
        __half2 h2 = __floats2half2_rn(v1.x, v1.y);
        __half2 h3 = __floats2half2_rn(v1.z, v1.w);
        uint4 u;
        u.x = *reinterpret_cast<uint32_t*>(&h0);
        u.y = *reinterpret_cast<uint32_t*>(&h1);
        u.z = *reinterpret_cast<uint32_t*>(&h2);
        u.w = *reinterpret_cast<uint32_t*>(&h3);
        *reinterpret_cast<uint4*>(dst + col) = u;
    }
}

// ---------------- split-K fp16 GEMM: 128x128 tile, 4 warps of 64x64, 2 CTAs/SM ----------------
__global__ __launch_bounds__(128, 2) void gemm_splitk(void)
{
    extern __shared__ __align__(16) char smem[];
    const uint32_t smem_u = (uint32_t)__cvta_generic_to_shared(smem);

    const int tid  = threadIdx.x;
    const int lane = tid & 31;
    const int warp = tid >> 5;
    const int wm   = (warp & 1) * 64;        // 2 warps in M
    const int wn   = (warp >> 1) * 64;       // 2 warps in N
    const int n0   = blockIdx.x * BN;
    const int m0   = blockIdx.y * BM;
    const int sk   = blockIdx.z;             // split index 0/1
    const int kbase = sk * KHALF;

    const __half* gA = g_Z  + (size_t)m0 * KTOT + kbase;
    const __half* gB = g_WB + (size_t)n0 * KTOT + kbase;

    // loader: rows of 128B = 8 chunks; 128 threads = 16 rows/iter
    const int lr = tid >> 3;                 // 0..15
    const int lcb = (tid & 7) << 4;          // 0..112

    const uint32_t aOff = (uint32_t)((wm + (lane & 7) + ((lane >> 3) & 1) * 8) * ROWB
                                     + (lane >> 4) * 16);
    const uint32_t bOff = (uint32_t)(A_BYTES
                                     + (wn + (lane & 7) + ((lane >> 4) & 1) * 8) * ROWB
                                     + ((lane >> 3) & 1) * 16);

    float acc[4][8][4];
#pragma unroll
    for (int t = 0; t < 4; t++)
#pragma unroll
        for (int u = 0; u < 8; u++)
#pragma unroll
            for (int v = 0; v < 4; v++) acc[t][u][v] = 0.f;

    auto load_stage = [&](int kt) {
        char* As = smem + (kt & 1) * STAGE_BYTES;
        char* Bs = As + A_BYTES;
        const int k0 = kt * BK;
#pragma unroll
        for (int i = 0; i < 8; i++) {
            int r = lr + i * 16;
            cp16(As + r * ROWB + lcb, (const char*)(gA + (size_t)r * KTOT + k0) + lcb);
        }
#pragma unroll
        for (int i = 0; i < 8; i++) {
            int r = lr + i * 16;
            cp16(Bs + r * ROWB + lcb, (const char*)(gB + (size_t)r * KTOT + k0) + lcb);
        }
    };

    load_stage(0);
    asm volatile("cp.async.commit_group;");

    uint32_t afr[2][4][4], bfr[2][4][4];

    for (int kt = 0; kt < KTILES; kt++) {
        asm volatile("cp.async.wait_group 0;");
        __syncthreads();

        if (kt + 1 < KTILES) {
            load_stage(kt + 1);
            asm volatile("cp.async.commit_group;");
        }

        const uint32_t stage = smem_u + (uint32_t)((kt & 1) * STAGE_BYTES);
        const uint32_t aBase = stage + aOff;
        const uint32_t bBase = stage + bOff;

        // prefetch ks=0 fragments
#pragma unroll
        for (int t = 0; t < 4; t++) ldsm4(aBase + t * (16 * ROWB), afr[0][t]);
#pragma unroll
        for (int j = 0; j < 4; j++) ldsm4(bBase + j * (16 * ROWB), bfr[0][j]);

#pragma unroll
        for (int ks = 0; ks < 4; ks++) {     // each ks = k16 (32B)
            const int cur = ks & 1, nxt = cur ^ 1;
            if (ks < 3) {
#pragma unroll
                for (int t = 0; t < 4; t++)
                    ldsm4(aBase + (ks + 1) * 32 + t * (16 * ROWB), afr[nxt][t]);
#pragma unroll
                for (int j = 0; j < 4; j++)
                    ldsm4(bBase + (ks + 1) * 32 + j * (16 * ROWB), bfr[nxt][j]);
            }
#pragma unroll
            for (int t = 0; t < 4; t++)
#pragma unroll
                for (int u = 0; u < 8; u++) {
                    const int j = u >> 1;
                    const uint32_t b0 = (u & 1) ? bfr[cur][j][2] : bfr[cur][j][0];
                    const uint32_t b1 = (u & 1) ? bfr[cur][j][3] : bfr[cur][j][1];
                    asm volatile(
                        "mma.sync.aligned.m16n8k16.row.col.f32.f16.f16.f32 "
                        "{%0,%1,%2,%3},{%4,%5,%6,%7},{%8,%9},{%0,%1,%2,%3};"
                        : "+f"(acc[t][u][0]), "+f"(acc[t][u][1]),
                          "+f"(acc[t][u][2]), "+f"(acc[t][u][3])
                        : "r"(afr[cur][t][0]), "r"(afr[cur][t][1]),
                          "r"(afr[cur][t][2]), "r"(afr[cur][t][3]),
                          "r"(b0), "r"(b1));
                }
        }
    }

    // ---- store partial tile to this split's proj buffer ----
    float* proj = g_proj[sk];
#pragma unroll
    for (int t = 0; t < 4; t++) {
        int r = m0 + wm + t * 16 + (lane >> 2);
#pragma unroll
        for (int u = 0; u < 8; u++) {
            int c = n0 + wn + u * 8 + ((lane & 3) << 1);
            *reinterpret_cast<float2*>(&proj[(size_t)r * NTOT + c]) =
                make_float2(acc[t][u][0], acc[t][u][1]);
            *reinterpret_cast<float2*>(&proj[(size_t)(r + 8) * NTOT + c]) =
                make_float2(acc[t][u][2], acc[t][u][3]);
        }
    }
}

// ---------------- gate epilogue: combine split-K partials + LSTM ----------------
__global__ __launch_bounds__(256) void gate_kernel(
    const float* __restrict__ old_state,
    const float* __restrict__ bi, const float* __restrict__ bf,
    const float* __restrict__ bo, const float* __restrict__ bs,
    float* __restrict__ out)
{
    int idx = blockIdx.x * 256 + threadIdx.x;   // 0 .. 2048*1024-1
    int b = idx >> 10;
    int h = idx & 1023;

    // proj columns are gate-interleaved: col = h*4 + gate -> one float4 = all gates
    float4 p0 = *reinterpret_cast<const float4*>(&g_proj[0][(size_t)b * NTOT + h * 4]);
    float4 p1 = *reinterpret_cast<const float4*>(&g_proj[1][(size_t)b * NTOT + h * 4]);

    float gi = p0.x + p1.x + __ldg(bi + h);
    float gf = p0.y + p1.y + __ldg(bf + h);
    float go = p0.z + p1.z + __ldg(bo + h);
    float gs = p0.w + p1.w + __ldg(bs + h);

    float c  = __ldg(old_state + (size_t)b * HDIM + h);
    float ns = sigm(gf) * c + sigm(gi) * tanhf(gs);
    out[(size_t)b * HDIM + h] = sigm(go) * tanhf(ns);
}

extern "C" void kernel_launch(void* const* d_in, const int* in_sizes, int n_in,
                              void* d_out, int out_size)
{
    const float* x  = (const float*)d_in[0];
    const float* pt = (const float*)d_in[1];
    const float* pl = (const float*)d_in[2];
    const float* os = (const float*)d_in[3];
    const float* Wi = (const float*)d_in[4];
    const float* bi = (const float*)d_in[5];
    const float* Wf = (const float*)d_in[6];
    const float* bf = (const float*)d_in[7];
    const float* Wo = (const float*)d_in[8];
    const float* bo = (const float*)d_in[9];
    const float* Ws = (const float*)d_in[10];
    const float* bs = (const float*)d_in[11];
    float* out = (float*)d_out;

    cudaFuncSetAttribute(gemm_splitk, cudaFuncAttributeMaxDynamicSharedMemorySize, SMEM_BYTES);

    conv_all<<<1184, 256>>>(x, pt, pl, Wi, Wf, Wo, Ws);
    gemm_splitk<<<dim3(NTOT / BN, MTOT / BM, 2), 128, SMEM_BYTES>>>();
    gate_kernel<<<(MTOT * HDIM) / 256, 256>>>(os, bi, bf, bo, bs, out);
}

// round 16
// speedup vs baseline: 1.2894x; 1.0517x over previous
#include <cuda_runtime.h>
#include <cuda_fp16.h>
#include <cstdint>
#include <cstddef>

#define MTOT 2048
#define NTOT 4096
#define KTOT 4352
#define HDIM 1024
#define XDIM 2304

#define BM 64
#define BN 128
#define BK 64                                   // halves per K-tile
#define ROWB 144                                // 128B data + 16B pad
#define A_BYTES (BM * ROWB)                     // 9216
#define B_BYTES (BN * ROWB)                     // 18432
#define STAGE_BYTES (A_BYTES + B_BYTES)         // 27648
#define BIAS_BYTE_OFF (2 * STAGE_BYTES)         // 55296
#define SMEM_BYTES (BIAS_BYTE_OFF + 512)        // 55808
#define KTILES (KTOT / BK)                      // 68

__device__ __half g_Z[(size_t)MTOT * KTOT];
__device__ __half g_WB[(size_t)NTOT * KTOT];

__device__ __forceinline__ void cp16(void* sdst, const void* gsrc) {
    uint32_t s = (uint32_t)__cvta_generic_to_shared(sdst);
    asm volatile("cp.async.cg.shared.global [%0], [%1], 16;" :: "r"(s), "l"(gsrc));
}

__device__ __forceinline__ void ldsm4(uint32_t addr, uint32_t* r) {
    asm volatile("ldmatrix.sync.aligned.m8n8.x4.shared.b16 {%0,%1,%2,%3}, [%4];"
                 : "=r"(r[0]), "=r"(r[1]), "=r"(r[2]), "=r"(r[3]) : "r"(addr));
}

__device__ __forceinline__ float sigm(float v) { return 1.0f / (1.0f + __expf(-v)); }

// ---------------- merged grid-stride convert kernel (32B per iter) ----------------
// y<MTOT -> g_Z row (concat x|pt|pl); else g_WB row g = n_tile*128 + h_local*4 + gate
#define C8_PER_ROW (KTOT / 8)                   // 544
#define CONV_TOTAL ((MTOT + NTOT) * C8_PER_ROW)

__global__ __launch_bounds__(256) void conv_all(
    const float* __restrict__ x, const float* __restrict__ pt, const float* __restrict__ pl,
    const float* __restrict__ Wi, const float* __restrict__ Wf,
    const float* __restrict__ Wo, const float* __restrict__ Ws)
{
    for (int idx = blockIdx.x * blockDim.x + threadIdx.x; idx < CONV_TOTAL;
         idx += gridDim.x * blockDim.x) {
        int y = idx / C8_PER_ROW;
        int c8 = idx - y * C8_PER_ROW;
        int col = c8 * 8;

        const float* src;
        __half* dst;
        if (y < MTOT) {
            int cc;
            if (col < XDIM)             { src = x  + (size_t)y * XDIM; cc = col; }
            else if (col < XDIM + HDIM) { src = pt + (size_t)y * HDIM; cc = col - XDIM; }
            else                        { src = pl + (size_t)y * HDIM; cc = col - XDIM - HDIM; }
            src += cc - col;
            dst = g_Z + (size_t)y * KTOT;
        } else {
            int g = y - MTOT;
            int n_tile = g >> 7, r = g & 127;        // 128-row CTA blocks
            int h = n_tile * 32 + (r >> 2);
            int gate = r & 3;
            const float* W = (gate == 0) ? Wi : (gate == 1) ? Wf : (gate == 2) ? Wo : Ws;
            src = W + (size_t)h * KTOT;
            dst = g_WB + (size_t)g * KTOT;
        }

        float4 v0 = *reinterpret_cast<const float4*>(src + col);
        float4 v1 = *reinterpret_cast<const float4*>(src + col + 4);
        __half2 h0 = __floats2half2_rn(v0.x, v0.y);
        __half2 h1 = __floats2half2_rn(v0.z, v0.w);
        __half2 h2 = __floats2half2_rn(v1.x, v1.y);
        __half2 h3 = __floats2half2_rn(v1.z, v1.w);
        uint4 u;
        u.x = *reinterpret_cast<uint32_t*>(&h0);
        u.y = *reinterpret_cast<uint32_t*>(&h1);
        u.z = *reinterpret_cast<uint32_t*>(&h2);
        u.w = *reinterpret_cast<uint32_t*>(&h3);
        *reinterpret_cast<uint4*>(dst + col) = u;
    }
}

// ---------------- fp16 GEMM + fused LSTM: 64x128 tile, 2 warps of 64x64, 4 CTAs/SM ----------------
__global__ __launch_bounds__(64, 4) void gemm_lstm(
    const float* __restrict__ old_state,
    const float* __restrict__ bi, const float* __restrict__ bf,
    const float* __restrict__ bo, const float* __restrict__ bs,
    float* __restrict__ out)
{
    extern __shared__ __align__(16) char smem[];
    const uint32_t smem_u = (uint32_t)__cvta_generic_to_shared(smem);

    const int tid  = threadIdx.x;
    const int lane = tid & 31;
    const int warp = tid >> 5;               // 0..1
    const int wn   = warp * 64;              // 2 warps in N
    const int m0   = blockIdx.y * BM;
    const int n_tile = blockIdx.x;
    const int h0   = n_tile * 32;            // 32 hidden units per CTA

    const __half* gA = g_Z  + (size_t)m0 * KTOT;
    const __half* gB = g_WB + (size_t)(n_tile * BN) * KTOT;

    float* bias_sm = reinterpret_cast<float*>(smem + BIAS_BYTE_OFF);   // [32][4]
    {
        // 128 entries, 64 threads -> 2 each
        int i0 = tid, i1 = tid + 64;
        int hl0 = i0 >> 2, g0 = i0 & 3;
        int hl1 = i1 >> 2, g1 = i1 & 3;
        const float* b0p = (g0 == 0) ? bi : (g0 == 1) ? bf : (g0 == 2) ? bo : bs;
        const float* b1p = (g1 == 0) ? bi : (g1 == 1) ? bf : (g1 == 2) ? bo : bs;
        bias_sm[i0] = b0p[h0 + hl0];
        bias_sm[i1] = b1p[h0 + hl1];
    }

    // loader: rows of 128B = 8 chunks; 64 threads = 8 rows/iter
    const int lr = tid >> 3;                 // 0..7
    const int lcb = (tid & 7) << 4;          // 0..112

    const uint32_t aOff = (uint32_t)(((lane & 7) + ((lane >> 3) & 1) * 8) * ROWB
                                     + (lane >> 4) * 16);
    const uint32_t bOff = (uint32_t)(A_BYTES
                                     + (wn + (lane & 7) + ((lane >> 4) & 1) * 8) * ROWB
                                     + ((lane >> 3) & 1) * 16);

    float acc[4][8][4];
#pragma unroll
    for (int t = 0; t < 4; t++)
#pragma unroll
        for (int u = 0; u < 8; u++)
#pragma unroll
            for (int v = 0; v < 4; v++) acc[t][u][v] = 0.f;

    auto load_stage = [&](int kt) {
        char* As = smem + (kt & 1) * STAGE_BYTES;
        char* Bs = As + A_BYTES;
        const int k0 = kt * BK;
#pragma unroll
        for (int i = 0; i < 8; i++) {
            int r = lr + i * 8;
            cp16(As + r * ROWB + lcb, (const char*)(gA + (size_t)r * KTOT + k0) + lcb);
        }
#pragma unroll
        for (int i = 0; i < 16; i++) {
            int r = lr + i * 8;
            cp16(Bs + r * ROWB + lcb, (const char*)(gB + (size_t)r * KTOT + k0) + lcb);
        }
    };

    load_stage(0);
    asm volatile("cp.async.commit_group;");

    uint32_t afr[2][4][4], bfr[2][4][4];

    for (int kt = 0; kt < KTILES; kt++) {
        asm volatile("cp.async.wait_group 0;");
        __syncthreads();

        if (kt + 1 < KTILES) {
            load_stage(kt + 1);
            asm volatile("cp.async.commit_group;");
        }

        const uint32_t stage = smem_u + (uint32_t)((kt & 1) * STAGE_BYTES);
        const uint32_t aBase = stage + aOff;
        const uint32_t bBase = stage + bOff;

        // prefetch ks=0 fragments
#pragma unroll
        for (int t = 0; t < 4; t++) ldsm4(aBase + t * (16 * ROWB), afr[0][t]);
#pragma unroll
        for (int j = 0; j < 4; j++) ldsm4(bBase + j * (16 * ROWB), bfr[0][j]);

#pragma unroll
        for (int ks = 0; ks < 4; ks++) {     // each ks = k16 (32B)
            const int cur = ks & 1, nxt = cur ^ 1;
            if (ks < 3) {
#pragma unroll
                for (int t = 0; t < 4; t++)
                    ldsm4(aBase + (ks + 1) * 32 + t * (16 * ROWB), afr[nxt][t]);
#pragma unroll
                for (int j = 0; j < 4; j++)
                    ldsm4(bBase + (ks + 1) * 32 + j * (16 * ROWB), bfr[nxt][j]);
            }
#pragma unroll
            for (int t = 0; t < 4; t++)
#pragma unroll
                for (int u = 0; u < 8; u++) {
                    const int j = u >> 1;
                    const uint32_t b0 = (u & 1) ? bfr[cur][j][2] : bfr[cur][j][0];
                    const uint32_t b1 = (u & 1) ? bfr[cur][j][3] : bfr[cur][j][1];
                    asm volatile(
                        "mma.sync.aligned.m16n8k16.row.col.f32.f16.f16.f32 "
                        "{%0,%1,%2,%3},{%4,%5,%6,%7},{%8,%9},{%0,%1,%2,%3};"
                        : "+f"(acc[t][u][0]), "+f"(acc[t][u][1]),
                          "+f"(acc[t][u][2]), "+f"(acc[t][u][3])
                        : "r"(afr[cur][t][0]), "r"(afr[cur][t][1]),
                          "r"(afr[cur][t][2]), "r"(afr[cur][t][3]),
                          "r"(b0), "r"(b1));
                }
        }
    }

    // ---- fused LSTM gate epilogue ----
    const int hadj = (lane & 3) >> 1;
    const int row_sel = (lane & 1) << 3;
#pragma unroll
    for (int t = 0; t < 4; t++) {
        int r_out = m0 + t * 16 + (lane >> 2) + row_sel;
        const float* oldr = old_state + (size_t)r_out * HDIM + h0;
        float*       outr = out       + (size_t)r_out * HDIM + h0;
#pragma unroll
        for (int u = 0; u < 8; u++) {
            float v0 = acc[t][u][0], v1 = acc[t][u][1];
            float v2 = acc[t][u][2], v3 = acc[t][u][3];
            float t0 = (lane & 1) ? v0 : v2;
            float t1 = (lane & 1) ? v1 : v3;
            float e0 = __shfl_xor_sync(0xffffffffu, t0, 1);
            float e1 = __shfl_xor_sync(0xffffffffu, t1, 1);
            float gi, gf, go, gs;
            if (lane & 1) { gi = e0; gf = e1; go = v2; gs = v3; }
            else          { gi = v0; gf = v1; go = e0; gs = e1; }
            int hl = ((wn + u * 8) >> 2) + hadj;    // 0..31
            gi += bias_sm[hl * 4 + 0];
            gf += bias_sm[hl * 4 + 1];
            go += bias_sm[hl * 4 + 2];
            gs += bias_sm[hl * 4 + 3];
            float c  = __ldg(oldr + hl);
            float ns = sigm(gf) * c + sigm(gi) * tanhf(gs);
            outr[hl] = sigm(go) * tanhf(ns);
        }
    }
}

extern "C" void kernel_launch(void* const* d_in, const int* in_sizes, int n_in,
                              void* d_out, int out_size)
{
    const float* x  = (const float*)d_in[0];
    const float* pt = (const float*)d_in[1];
    const float* pl = (const float*)d_in[2];
    const float* os = (const float*)d_in[3];
    const float* Wi = (const float*)d_in[4];
    const float* bi = (const float*)d_in[5];
    const float* Wf = (const float*)d_in[6];
    const float* bf = (const float*)d_in[7];
    const float* Wo = (const float*)d_in[8];
    const float* bo = (const float*)d_in[9];
    const float* Ws = (const float*)d_in[10];
    const float* bs = (const float*)d_in[11];
    float* out = (float*)d_out;

    cudaFuncSetAttribute(gemm_lstm, cudaFuncAttributeMaxDynamicSharedMemorySize, SMEM_BYTES);

    conv_all<<<1184, 256>>>(x, pt, pl, Wi, Wf, Wo, Ws);
    gemm_lstm<<<dim3(NTOT / BN, MTOT / BM), 64, SMEM_BYTES>>>(os, bi, bf, bo, bs, out);
}